// round 13
// baseline (speedup 1.0000x reference)
#include <cuda_runtime.h>
#include <cstdint>

#define MAX_E 100000
#define MAX_T 1000000
#define CCH   64
#define SCAN_BLK 512
#define MAX_SCAN_BLOCKS ((MAX_E + SCAN_BLK - 1) / SCAN_BLK)
#define SLOTS 128   // CSR slots per pass1 block (2 threads per slot)
#define TPBH  256   // pass1 threads per block
#define RS    65    // padded smem row stride (odd => conflict-free per half)

// Scratch (device globals — zero at module load; g_cnt/g_cursor re-zeroed by
// k_edge at the end of every run => zero on entry for every replay).
__device__ float4   g_rnorm4[MAX_E];
__device__ unsigned g_cnt[MAX_E];
__device__ unsigned g_off[MAX_E];    // block-local exclusive prefix (scan1)
__device__ unsigned g_cursor[MAX_E];
__device__ unsigned g_bsum[MAX_SCAN_BLOCKS];  // exclusive block offsets (scan2)
__device__ int4     g_pack[MAX_T];   // {src, dst, cos_theta bits, 0}, CSR-ordered
__device__ int2     g_se[MAX_T];     // {src, exp(logit) bits}, CSR-ordered

// ---------------------------------------------------------------------------
__global__ void k_prep_count(const float* __restrict__ r,
                             const int* __restrict__ tdst, int E, int T) {
    int i = blockIdx.x * blockDim.x + threadIdx.x;
    if (i < E) {
        float x = r[3 * i + 0], y = r[3 * i + 1], z = r[3 * i + 2];
        float inv = rsqrtf(x * x + y * y + z * z);
        g_rnorm4[i] = make_float4(x * inv, y * inv, z * inv, 0.0f);
    }
    if (i < T) atomicAdd(&g_cnt[tdst[i]], 1u);
}

// -------- 2-kernel scan; final block-offset add folded into consumers -------
__global__ void k_scan1(int E) {
    __shared__ unsigned sh[SCAN_BLK];
    int i = blockIdx.x * SCAN_BLK + threadIdx.x;
    unsigned v = (i < E) ? g_cnt[i] : 0u;
    sh[threadIdx.x] = v;
    __syncthreads();
    unsigned incl = v;
    for (int ofs = 1; ofs < SCAN_BLK; ofs <<= 1) {
        unsigned add = (threadIdx.x >= ofs) ? sh[threadIdx.x - ofs] : 0u;
        __syncthreads();
        incl += add;
        sh[threadIdx.x] = incl;
        __syncthreads();
    }
    if (i < E) g_off[i] = incl - v;
    if (threadIdx.x == SCAN_BLK - 1) g_bsum[blockIdx.x] = incl;
}

__global__ void k_scan2(int nb) {
    __shared__ unsigned sh[SCAN_BLK];
    unsigned v = (threadIdx.x < nb) ? g_bsum[threadIdx.x] : 0u;
    sh[threadIdx.x] = v;
    __syncthreads();
    unsigned incl = v;
    for (int ofs = 1; ofs < SCAN_BLK; ofs <<= 1) {
        unsigned add = (threadIdx.x >= ofs) ? sh[threadIdx.x - ofs] : 0u;
        __syncthreads();
        incl += add;
        sh[threadIdx.x] = incl;
        __syncthreads();
    }
    if (threadIdx.x < nb) g_bsum[threadIdx.x] = incl - v;
}

__device__ __forceinline__ unsigned edge_base(int e) {
    return g_off[e] + g_bsum[e >> 9];        // SCAN_BLK == 512
}

// ---------------------------------------------------------------------------
// perm: CSR scatter of packed {src, dst, cos(theta)} (one STG.128 per triplet)
// ---------------------------------------------------------------------------
__global__ void k_perm(const int* __restrict__ tsrc, const int* __restrict__ tdst, int T) {
    int t = blockIdx.x * blockDim.x + threadIdx.x;
    if (t >= T) return;
    int s = tsrc[t], d = tdst[t];
    unsigned pos = edge_base(d) + atomicAdd(&g_cursor[d], 1u);
    float4 rs = __ldg(&g_rnorm4[s]);
    float4 rd = __ldg(&g_rnorm4[d]);
    float cth = rs.x * rd.x + rs.y * rd.y + rs.z * rd.z;
    cth = fminf(fmaxf(cth, -1.0f + 1e-6f), 1.0f - 1e-6f);
    g_pack[pos] = make_int4(s, d, __float_as_int(cth), 0);
}

// ---------------------------------------------------------------------------
// pass1: exp(logit) per CSR slot, 2 THREADS PER SLOT (lane pair).
//  - even lane: channels 0..31, odd lane: 32..63; logits joined via shfl.
//  - odd lane seeds Chebyshev at (T_31, T_32): z^32 by 5 complex squarings of
//    (cos th + i sin th); T_31 = c32*c + s32*s.
//  - per-channel INDEPENDENT silu (__fdividef/__expf — proven fast form R5/R8;
//    batched variants regressed 2x in R11/R12: latency-bound, never lengthen
//    dependency chains here).
//  - xij[src] staged to smem; xij[dst] half-row via 8 LDG.128 in-loop.
//  No softmax max subtraction (|logit| << 88; alpha identical — R4-R12).
// ---------------------------------------------------------------------------
__global__ void __launch_bounds__(TPBH, 5)
k_pass1(const float* __restrict__ xij, const float* __restrict__ attn, int T) {
    __shared__ float sx[SLOTS * RS];
    __shared__ float sat[CCH];
    int tid = threadIdx.x;
    int base = blockIdx.x * SLOTS;
    if (tid < CCH) sat[tid] = attn[tid];

    int lane = tid & 31, w = tid >> 5;
    for (int j = w; j < SLOTS; j += TPBH / 32) {
        int t = base + j;
        if (t < T) {
            int s = __ldg(&g_pack[t].x);   // warp-uniform -> broadcast
            float2 v = __ldg((const float2*)(xij + (size_t)s * CCH) + lane);
            sx[j * RS + 2 * lane]     = v.x;
            sx[j * RS + 2 * lane + 1] = v.y;
        }
    }
    __syncthreads();

    int slotLocal = tid >> 1;
    int half = tid & 1;
    int slot = base + slotLocal;
    bool valid = (slot < T);
    int sIdx = valid ? slot : (T - 1);     // clamp: keep all lanes active

    int4 p = __ldg(&g_pack[sIdx]);
    float cth = __int_as_float(p.z);
    float c2 = 2.0f * cth;

    float zp, zc;
    if (half == 0) {
        zp = cth; zc = 1.0f;               // T_{-1}, T_0
    } else {
        float s2 = fmaf(-cth, cth, 1.0f);
        float sn = sqrtf(fmaxf(s2, 0.0f)); // sin(theta) >= 0
        float re = cth, im = sn;
#pragma unroll
        for (int q = 0; q < 5; q++) {      // (c+is)^32
            float r2 = fmaf(re, re, -(im * im));
            im = 2.0f * re * im;
            re = r2;
        }
        zc = re;                           // T_32 = cos(32 th)
        zp = fmaf(re, cth, im * sn);       // T_31 = cos(32th - th)
    }

    const float* row = &sx[slotLocal * RS + half * 32];
    const float4* xd = (const float4*)(xij + (size_t)p.y * CCH + half * 32);
    const float* satH = &sat[half * 32];
    float a = 0.0f;

#pragma unroll
    for (int k = 0; k < 8; k++) {
        float4 Dv = __ldg(xd + k);
        float dv[4] = {Dv.x, Dv.y, Dv.z, Dv.w};
#pragma unroll
        for (int q = 0; q < 4; q++) {
            int c = 4 * k + q;
            float v = zc + row[c] + dv[q];
            float e = __fdividef(v, 1.0f + __expf(-v));   // silu (independent)
            a = fmaf(e, satH[c], a);
            float zn = fmaf(c2, zc, -zp);                 // Chebyshev step
            zp = zc; zc = zn;
        }
    }

    a += __shfl_xor_sync(0xFFFFFFFFu, a, 1);              // pair-join
    if (valid && half == 0)
        g_se[slot] = make_int2(p.x, __float_as_int(__expf(a)));
}

// ---------------------------------------------------------------------------
// edge: warp-per-edge aggregate: ft = (sum ex*x[src]) / sum ex.
// Lane owns channels {2*lane, 2*lane+1}. Restores g_cnt/g_cursor to zero.
// ---------------------------------------------------------------------------
__global__ void __launch_bounds__(256)
k_edge(const float* __restrict__ xij, float* __restrict__ ft, int E) {
    int warp = (blockIdx.x * blockDim.x + threadIdx.x) >> 5;
    int lane = threadIdx.x & 31;
    if (warp >= E) return;

    int base = (int)edge_base(warp);
    int deg  = (int)g_cnt[warp];
    if (lane == 0) { g_cnt[warp] = 0u; g_cursor[warp] = 0u; }

    float ax = 0.0f, ay = 0.0f, den = 0.0f;

    int i = 0;
    for (; i + 4 <= deg; i += 4) {
        int2 p0 = __ldg(&g_se[base + i + 0]);
        int2 p1 = __ldg(&g_se[base + i + 1]);
        int2 p2 = __ldg(&g_se[base + i + 2]);
        int2 p3 = __ldg(&g_se[base + i + 3]);
        float2 v0 = __ldg((const float2*)(xij + (size_t)p0.x * CCH) + lane);
        float2 v1 = __ldg((const float2*)(xij + (size_t)p1.x * CCH) + lane);
        float2 v2 = __ldg((const float2*)(xij + (size_t)p2.x * CCH) + lane);
        float2 v3 = __ldg((const float2*)(xij + (size_t)p3.x * CCH) + lane);
        float e0 = __int_as_float(p0.y), e1 = __int_as_float(p1.y);
        float e2 = __int_as_float(p2.y), e3 = __int_as_float(p3.y);
        den += (e0 + e1) + (e2 + e3);
        ax = fmaf(e0, v0.x, ax); ay = fmaf(e0, v0.y, ay);
        ax = fmaf(e1, v1.x, ax); ay = fmaf(e1, v1.y, ay);
        ax = fmaf(e2, v2.x, ax); ay = fmaf(e2, v2.y, ay);
        ax = fmaf(e3, v3.x, ax); ay = fmaf(e3, v3.y, ay);
    }
    for (; i < deg; i++) {
        int2 p0 = __ldg(&g_se[base + i]);
        float2 v0 = __ldg((const float2*)(xij + (size_t)p0.x * CCH) + lane);
        float e0 = __int_as_float(p0.y);
        den += e0;
        ax = fmaf(e0, v0.x, ax); ay = fmaf(e0, v0.y, ay);
    }

    float inv = (deg > 0) ? __fdividef(1.0f, den) : 0.0f;
    *((float2*)(ft + (size_t)warp * CCH) + lane) = make_float2(ax * inv, ay * inv);
}

// ---------------------------------------------------------------------------
extern "C" void kernel_launch(void* const* d_in, const int* in_sizes, int n_in,
                              void* d_out, int out_size) {
    const float* xij  = (const float*)d_in[0];
    const float* r    = (const float*)d_in[1];
    const float* attn = (const float*)d_in[2];
    const int*   tsrc = (const int*)d_in[3];
    const int*   tdst = (const int*)d_in[4];
    float* ft = (float*)d_out;

    int E = in_sizes[1] / 3;
    int T = in_sizes[3];
    int nsb = (E + SCAN_BLK - 1) / SCAN_BLK;
    int nmx = (T > E) ? T : E;

    k_prep_count<<<(nmx + 255) / 256, 256>>>(r, tdst, E, T);
    k_scan1<<<nsb, SCAN_BLK>>>(E);
    k_scan2<<<1,   SCAN_BLK>>>(nsb);
    k_perm <<<(T + 255) / 256, 256>>>(tsrc, tdst, T);
    k_pass1<<<(T + SLOTS - 1) / SLOTS, TPBH>>>(xij, attn, T);
    k_edge <<<(E * 32 + 255) / 256, 256>>>(xij, ft, E);
}

// round 14
// speedup vs baseline: 1.2279x; 1.2279x over previous
#include <cuda_runtime.h>
#include <cstdint>

#define MAX_E 100000
#define MAX_T 1000000
#define CCH   64
#define SCAN_BLK 512
#define MAX_SCAN_BLOCKS ((MAX_E + SCAN_BLK - 1) / SCAN_BLK)
#define TPB1 128   // pass1: triplets per block
#define RS   65    // padded smem row stride (odd => conflict-free)

// Scratch (device globals — zero at module load; g_cnt/g_cursor re-zeroed by
// k_edge at the end of every run => zero on entry for every replay).
__device__ float4   g_rnorm4[MAX_E];
__device__ unsigned g_cnt[MAX_E];
__device__ unsigned g_off[MAX_E];    // block-local exclusive prefix (scan1)
__device__ unsigned g_cursor[MAX_E];
__device__ unsigned g_bsum[MAX_SCAN_BLOCKS];  // exclusive block offsets (scan2)
__device__ int      g_csrc[MAX_T];   // src ids, CSR(dst)-ordered
__device__ int      g_cdst[MAX_T];   // dst ids, CSR(dst)-ordered
__device__ int2     g_se[MAX_T];     // {src, exp(logit) bits}, CSR-ordered

// ---------------------------------------------------------------------------
// prep+count: unit bond dirs (negation cancels in src·dst dot) + degree histo
// ---------------------------------------------------------------------------
__global__ void k_prep_count(const float* __restrict__ r,
                             const int* __restrict__ tdst, int E, int T) {
    int i = blockIdx.x * blockDim.x + threadIdx.x;
    if (i < E) {
        float x = r[3 * i + 0], y = r[3 * i + 1], z = r[3 * i + 2];
        float inv = rsqrtf(x * x + y * y + z * z);
        g_rnorm4[i] = make_float4(x * inv, y * inv, z * inv, 0.0f);
    }
    if (i < T) atomicAdd(&g_cnt[tdst[i]], 1u);
}

// -------- 2-kernel scan; final block-offset add folded into consumers -------
__global__ void k_scan1(int E) {
    __shared__ unsigned sh[SCAN_BLK];
    int i = blockIdx.x * SCAN_BLK + threadIdx.x;
    unsigned v = (i < E) ? g_cnt[i] : 0u;
    sh[threadIdx.x] = v;
    __syncthreads();
    unsigned incl = v;
    for (int ofs = 1; ofs < SCAN_BLK; ofs <<= 1) {
        unsigned add = (threadIdx.x >= ofs) ? sh[threadIdx.x - ofs] : 0u;
        __syncthreads();
        incl += add;
        sh[threadIdx.x] = incl;
        __syncthreads();
    }
    if (i < E) g_off[i] = incl - v;          // block-local exclusive
    if (threadIdx.x == SCAN_BLK - 1) g_bsum[blockIdx.x] = incl;
}

__global__ void k_scan2(int nb) {
    __shared__ unsigned sh[SCAN_BLK];
    unsigned v = (threadIdx.x < nb) ? g_bsum[threadIdx.x] : 0u;
    sh[threadIdx.x] = v;
    __syncthreads();
    unsigned incl = v;
    for (int ofs = 1; ofs < SCAN_BLK; ofs <<= 1) {
        unsigned add = (threadIdx.x >= ofs) ? sh[threadIdx.x - ofs] : 0u;
        __syncthreads();
        incl += add;
        sh[threadIdx.x] = incl;
        __syncthreads();
    }
    if (threadIdx.x < nb) g_bsum[threadIdx.x] = incl - v;
}

__device__ __forceinline__ unsigned edge_base(int e) {
    return g_off[e] + g_bsum[e >> 9];        // SCAN_BLK == 512
}

// ---------------------------------------------------------------------------
// perm: scatter triplets into CSR(dst) order (R5 form — no cth here;
// cth-in-perm measured slower overall in R8 vs R5)
// ---------------------------------------------------------------------------
__global__ void k_perm(const int* __restrict__ tsrc, const int* __restrict__ tdst, int T) {
    int t = blockIdx.x * blockDim.x + threadIdx.x;
    if (t >= T) return;
    int d = tdst[t];
    unsigned pos = edge_base(d) + atomicAdd(&g_cursor[d], 1u);
    g_csrc[pos] = tsrc[t];
    g_cdst[pos] = d;
}

// ---------------------------------------------------------------------------
// pass1 (R5-proven, verbatim): exp(logit) in CSR order.
//  - xij[src] staged to smem (coalesced, odd stride 65 -> conflict-free LDS)
//  - xij[dst] direct float4 loads inside compute loop (CSR adjacency -> few
//    distinct rows/warp, L1-hits; latency overlaps MUFU chain)
//  - cth computed inline from g_rnorm4
//  - Chebyshev 3-term recurrence (1 FMA/channel)
//  - per-channel INDEPENDENT silu (__fdividef/__expf intrinsics). Batched /
//    restructured variants regressed 2x in R10-R13: latency-bound — do not
//    lengthen dependency chains.
//  No softmax max subtraction (|logit| << 88; alpha identical — R4-R13).
// ---------------------------------------------------------------------------
__global__ void __launch_bounds__(TPB1)
k_pass1(const float* __restrict__ xij, const float* __restrict__ attn, int T) {
    __shared__ float sx[TPB1 * RS];
    __shared__ float sat[CCH];
    int tid = threadIdx.x;
    int base = blockIdx.x * TPB1;
    if (tid < CCH) sat[tid] = attn[tid];

    int lane = tid & 31, w = tid >> 5;
    for (int j = w; j < TPB1; j += TPB1 / 32) {
        int t = base + j;
        if (t < T) {
            int s = g_csrc[t];
            float2 v = __ldg((const float2*)(xij + (size_t)s * CCH) + lane);
            sx[j * RS + 2 * lane]     = v.x;
            sx[j * RS + 2 * lane + 1] = v.y;
        }
    }
    __syncthreads();

    int t = base + tid;
    if (t >= T) return;
    int s = g_csrc[t], d = g_cdst[t];

    float4 rs = __ldg(&g_rnorm4[s]);
    float4 rd = __ldg(&g_rnorm4[d]);
    float cth = rs.x * rd.x + rs.y * rd.y + rs.z * rd.z;
    cth = fminf(fmaxf(cth, -1.0f + 1e-6f), 1.0f - 1e-6f);
    float c2 = 2.0f * cth;
    float zp = cth, zc = 1.0f;   // T_{-1}, T_0

    const float4* xd = (const float4*)(xij + (size_t)d * CCH);
    const float* row = &sx[tid * RS];
    float a = 0.0f;

#pragma unroll
    for (int k = 0; k < CCH / 4; k++) {
        float4 D = __ldg(xd + k);
        float dv[4] = {D.x, D.y, D.z, D.w};
#pragma unroll
        for (int j = 0; j < 4; j++) {
            int c = 4 * k + j;
            float v = zc + row[c] + dv[j];
            float e = __fdividef(v, 1.0f + __expf(-v));   // silu
            a = fmaf(e, sat[c], a);
            float zn = fmaf(c2, zc, -zp);                 // Chebyshev step
            zp = zc; zc = zn;
        }
    }
    g_se[t] = make_int2(s, __float_as_int(__expf(a)));    // coalesced STG.64
}

// ---------------------------------------------------------------------------
// edge: warp-per-edge aggregate: ft = (sum ex*x[src]) / sum ex.
// Lane owns channels {2*lane, 2*lane+1}. Restores g_cnt/g_cursor to zero.
// ---------------------------------------------------------------------------
__global__ void __launch_bounds__(256)
k_edge(const float* __restrict__ xij, float* __restrict__ ft, int E) {
    int warp = (blockIdx.x * blockDim.x + threadIdx.x) >> 5;
    int lane = threadIdx.x & 31;
    if (warp >= E) return;

    int base = (int)edge_base(warp);
    int deg  = (int)g_cnt[warp];
    if (lane == 0) { g_cnt[warp] = 0u; g_cursor[warp] = 0u; }

    float ax = 0.0f, ay = 0.0f, den = 0.0f;

    int i = 0;
    for (; i + 4 <= deg; i += 4) {
        int2 p0 = __ldg(&g_se[base + i + 0]);
        int2 p1 = __ldg(&g_se[base + i + 1]);
        int2 p2 = __ldg(&g_se[base + i + 2]);
        int2 p3 = __ldg(&g_se[base + i + 3]);
        float2 v0 = __ldg((const float2*)(xij + (size_t)p0.x * CCH) + lane);
        float2 v1 = __ldg((const float2*)(xij + (size_t)p1.x * CCH) + lane);
        float2 v2 = __ldg((const float2*)(xij + (size_t)p2.x * CCH) + lane);
        float2 v3 = __ldg((const float2*)(xij + (size_t)p3.x * CCH) + lane);
        float e0 = __int_as_float(p0.y), e1 = __int_as_float(p1.y);
        float e2 = __int_as_float(p2.y), e3 = __int_as_float(p3.y);
        den += (e0 + e1) + (e2 + e3);
        ax = fmaf(e0, v0.x, ax); ay = fmaf(e0, v0.y, ay);
        ax = fmaf(e1, v1.x, ax); ay = fmaf(e1, v1.y, ay);
        ax = fmaf(e2, v2.x, ax); ay = fmaf(e2, v2.y, ay);
        ax = fmaf(e3, v3.x, ax); ay = fmaf(e3, v3.y, ay);
    }
    for (; i < deg; i++) {
        int2 p0 = __ldg(&g_se[base + i]);
        float2 v0 = __ldg((const float2*)(xij + (size_t)p0.x * CCH) + lane);
        float e0 = __int_as_float(p0.y);
        den += e0;
        ax = fmaf(e0, v0.x, ax); ay = fmaf(e0, v0.y, ay);
    }

    float inv = (deg > 0) ? __fdividef(1.0f, den) : 0.0f;
    *((float2*)(ft + (size_t)warp * CCH) + lane) = make_float2(ax * inv, ay * inv);
}

// ---------------------------------------------------------------------------
extern "C" void kernel_launch(void* const* d_in, const int* in_sizes, int n_in,
                              void* d_out, int out_size) {
    const float* xij  = (const float*)d_in[0];
    const float* r    = (const float*)d_in[1];
    const float* attn = (const float*)d_in[2];
    const int*   tsrc = (const int*)d_in[3];
    const int*   tdst = (const int*)d_in[4];
    float* ft = (float*)d_out;

    int E = in_sizes[1] / 3;
    int T = in_sizes[3];
    int nsb = (E + SCAN_BLK - 1) / SCAN_BLK;
    int nmx = (T > E) ? T : E;

    k_prep_count<<<(nmx + 255) / 256, 256>>>(r, tdst, E, T);
    k_scan1<<<nsb, SCAN_BLK>>>(E);
    k_scan2<<<1,   SCAN_BLK>>>(nsb);
    k_perm <<<(T + 255) / 256, 256>>>(tsrc, tdst, T);
    k_pass1<<<(T + TPB1 - 1) / TPB1, TPB1>>>(xij, attn, T);
    k_edge <<<(E * 32 + 255) / 256, 256>>>(xij, ft, E);
}

// round 15
// speedup vs baseline: 2.0366x; 1.6586x over previous
#include <cuda_runtime.h>
#include <cstdint>

#define MAX_E 100000
#define MAX_T 1000000
#define CCH   64
#define SCAN_BLK 512
#define MAX_SCAN_BLOCKS ((MAX_E + SCAN_BLK - 1) / SCAN_BLK)
#define TPB1 128   // pass1: triplets per block

// Scratch (device globals — zero at module load; g_cnt/g_cursor are
// re-zeroed by k_edge at the end of every run => zero on entry always).
__device__ float4   g_rnorm4[MAX_E];
__device__ unsigned g_cnt[MAX_E];
__device__ unsigned g_off[MAX_E];
__device__ unsigned g_cursor[MAX_E];
__device__ unsigned g_bsum[MAX_SCAN_BLOCKS];
__device__ float    g_cex[MAX_T];    // exp(logit), CSR(dst)-ordered
__device__ int      g_csrc[MAX_T];   // src ids, CSR(dst)-ordered
__device__ int      g_cdst[MAX_T];   // dst ids, CSR(dst)-ordered

// ---------------------------------------------------------------------------
// prep+count fused: unit bond dirs for i<E; degree histogram for i<T
// ---------------------------------------------------------------------------
__global__ void k_prep_count(const float* __restrict__ r,
                             const int* __restrict__ tdst, int E, int T) {
    int i = blockIdx.x * blockDim.x + threadIdx.x;
    if (i < E) {
        float x = r[3 * i + 0], y = r[3 * i + 1], z = r[3 * i + 2];
        float inv = rsqrtf(x * x + y * y + z * z);
        g_rnorm4[i] = make_float4(x * inv, y * inv, z * inv, 0.0f);
    }
    if (i < T) atomicAdd(&g_cnt[tdst[i]], 1u);
}

// --------------------------- exclusive scan --------------------------------
__global__ void k_scan1(int E) {
    __shared__ unsigned sh[SCAN_BLK];
    int i = blockIdx.x * SCAN_BLK + threadIdx.x;
    unsigned v = (i < E) ? g_cnt[i] : 0u;
    sh[threadIdx.x] = v;
    __syncthreads();
    unsigned incl = v;
    for (int ofs = 1; ofs < SCAN_BLK; ofs <<= 1) {
        unsigned add = (threadIdx.x >= ofs) ? sh[threadIdx.x - ofs] : 0u;
        __syncthreads();
        incl += add;
        sh[threadIdx.x] = incl;
        __syncthreads();
    }
    if (i < E) g_off[i] = incl - v;
    if (threadIdx.x == SCAN_BLK - 1) g_bsum[blockIdx.x] = incl;
}

__global__ void k_scan2(int nb) {
    __shared__ unsigned sh[SCAN_BLK];
    unsigned v = (threadIdx.x < nb) ? g_bsum[threadIdx.x] : 0u;
    sh[threadIdx.x] = v;
    __syncthreads();
    unsigned incl = v;
    for (int ofs = 1; ofs < SCAN_BLK; ofs <<= 1) {
        unsigned add = (threadIdx.x >= ofs) ? sh[threadIdx.x - ofs] : 0u;
        __syncthreads();
        incl += add;
        sh[threadIdx.x] = incl;
        __syncthreads();
    }
    if (threadIdx.x < nb) g_bsum[threadIdx.x] = incl - v;
}

__global__ void k_scan3(int E) {
    int i = blockIdx.x * SCAN_BLK + threadIdx.x;
    if (i < E) g_off[i] += g_bsum[blockIdx.x];
}

// ---------------------------------------------------------------------------
// perm: scatter triplets into CSR(dst) order
// ---------------------------------------------------------------------------
__global__ void k_perm(const int* __restrict__ tsrc, const int* __restrict__ tdst, int T) {
    int t = blockIdx.x * blockDim.x + threadIdx.x;
    if (t >= T) return;
    int d = tdst[t];
    unsigned pos = g_off[d] + atomicAdd(&g_cursor[d], 1u);
    g_csrc[pos] = tsrc[t];
    g_cdst[pos] = d;
}

// ---------------------------------------------------------------------------
// pass1: exp(logit) in CSR order.
//  - xij[src] staged to smem (coalesced, odd stride 65)
//  - xij[dst] direct: CSR adjacency -> few distinct rows/warp, L1-hits
//  - Chebyshev 3-term recurrence (1 FMA/channel)
//  - stores exp(a): softmax needs no max subtraction (|a| << 88;
//    alpha = e^a / sum e^a identically — validated R4-R14)
// ---------------------------------------------------------------------------
__global__ void __launch_bounds__(TPB1)
k_pass1(const float* __restrict__ xij, const float* __restrict__ attn, int T) {
    __shared__ float sx[TPB1 * 65];
    __shared__ float sat[CCH];
    int tid = threadIdx.x;
    int base = blockIdx.x * TPB1;
    if (tid < CCH) sat[tid] = attn[tid];

    int lane = tid & 31, w = tid >> 5;
    for (int j = w; j < TPB1; j += TPB1 / 32) {
        int t = base + j;
        if (t < T) {
            int s = g_csrc[t];
            float2 v = __ldg((const float2*)(xij + (size_t)s * CCH) + lane);
            sx[j * 65 + 2 * lane]     = v.x;
            sx[j * 65 + 2 * lane + 1] = v.y;
        }
    }
    __syncthreads();

    int t = base + tid;
    if (t >= T) return;
    int s = g_csrc[t], d = g_cdst[t];

    float4 rs = __ldg(&g_rnorm4[s]);
    float4 rd = __ldg(&g_rnorm4[d]);
    float cth = rs.x * rd.x + rs.y * rd.y + rs.z * rd.z;
    cth = fminf(fmaxf(cth, -1.0f + 1e-6f), 1.0f - 1e-6f);
    float c2 = 2.0f * cth;
    float zp = cth, zc = 1.0f;   // T_{-1}, T_0

    const float4* xd = (const float4*)(xij + (size_t)d * CCH);
    const float* row = &sx[tid * 65];
    float a = 0.0f;

#pragma unroll
    for (int k = 0; k < CCH / 4; k++) {
        float4 D = __ldg(xd + k);
        float dv[4] = {D.x, D.y, D.z, D.w};
#pragma unroll
        for (int j = 0; j < 4; j++) {
            int c = 4 * k + j;
            float v = zc + row[c] + dv[j];
            float e = __fdividef(v, 1.0f + __expf(-v));   // silu
            a = fmaf(e, sat[c], a);
            float zn = fmaf(c2, zc, -zp);                 // Chebyshev step
            zp = zc; zc = zn;
        }
    }
    g_cex[t] = __expf(a);   // coalesced
}

// ---------------------------------------------------------------------------
// edge: warp-per-edge single-pass aggregate: ft = (sum ex*x[src]) / sum ex.
// Each lane owns channels {2*lane, 2*lane+1} (float2 loads/stores).
// Resets g_cnt / g_cursor for the next run (self-restoring global state).
// ---------------------------------------------------------------------------
__global__ void __launch_bounds__(256)
k_edge(const float* __restrict__ xij, float* __restrict__ ft, int E) {
    int warp = (blockIdx.x * blockDim.x + threadIdx.x) >> 5;
    int lane = threadIdx.x & 31;
    if (warp >= E) return;

    int base = (int)g_off[warp];
    int deg  = (int)g_cnt[warp];

    float ax = 0.0f, ay = 0.0f, den = 0.0f;

    int i = 0;
    for (; i + 4 <= deg; i += 4) {
        float e0 = g_cex[base + i + 0], e1 = g_cex[base + i + 1];
        float e2 = g_cex[base + i + 2], e3 = g_cex[base + i + 3];
        int s0 = g_csrc[base + i + 0], s1 = g_csrc[base + i + 1];
        int s2 = g_csrc[base + i + 2], s3 = g_csrc[base + i + 3];
        float2 v0 = __ldg((const float2*)(xij + (size_t)s0 * CCH) + lane);
        float2 v1 = __ldg((const float2*)(xij + (size_t)s1 * CCH) + lane);
        float2 v2 = __ldg((const float2*)(xij + (size_t)s2 * CCH) + lane);
        float2 v3 = __ldg((const float2*)(xij + (size_t)s3 * CCH) + lane);
        den += (e0 + e1) + (e2 + e3);
        ax = fmaf(e0, v0.x, ax); ay = fmaf(e0, v0.y, ay);
        ax = fmaf(e1, v1.x, ax); ay = fmaf(e1, v1.y, ay);
        ax = fmaf(e2, v2.x, ax); ay = fmaf(e2, v2.y, ay);
        ax = fmaf(e3, v3.x, ax); ay = fmaf(e3, v3.y, ay);
    }
    for (; i < deg; i++) {
        float e0 = g_cex[base + i];
        int s0 = g_csrc[base + i];
        float2 v0 = __ldg((const float2*)(xij + (size_t)s0 * CCH) + lane);
        den += e0;
        ax = fmaf(e0, v0.x, ax); ay = fmaf(e0, v0.y, ay);
    }

    float inv = (deg > 0) ? __fdividef(1.0f, den) : 0.0f;
    float2 out = make_float2(ax * inv, ay * inv);
    *((float2*)(ft + (size_t)warp * CCH) + lane) = out;

    if (lane == 0) {                // restore invariant for next run
        g_cnt[warp] = 0u;
        g_cursor[warp] = 0u;
    }
}

// ---------------------------------------------------------------------------
extern "C" void kernel_launch(void* const* d_in, const int* in_sizes, int n_in,
                              void* d_out, int out_size) {
    const float* xij  = (const float*)d_in[0];
    const float* r    = (const float*)d_in[1];
    const float* attn = (const float*)d_in[2];
    const int*   tsrc = (const int*)d_in[3];
    const int*   tdst = (const int*)d_in[4];
    float* ft = (float*)d_out;

    int E = in_sizes[1] / 3;
    int T = in_sizes[3];
    int nsb = (E + SCAN_BLK - 1) / SCAN_BLK;
    int nmx = (T > E) ? T : E;

    k_prep_count<<<(nmx + 255) / 256, 256>>>(r, tdst, E, T);
    k_scan1<<<nsb, SCAN_BLK>>>(E);
    k_scan2<<<1,   SCAN_BLK>>>(nsb);
    k_scan3<<<nsb, SCAN_BLK>>>(E);
    k_perm <<<(T + 255) / 256, 256>>>(tsrc, tdst, T);
    k_pass1<<<(T + TPB1 - 1) / TPB1, TPB1>>>(xij, attn, T);
    k_edge <<<(E * 32 + 255) / 256, 256>>>(xij, ft, E);
}

// round 16
// speedup vs baseline: 2.0641x; 1.0135x over previous
#include <cuda_runtime.h>
#include <cstdint>

#define MAX_E 100000
#define MAX_T 1000000
#define CCH   64
#define SCAN_BLK 512
#define MAX_SCAN_BLOCKS ((MAX_E + SCAN_BLK - 1) / SCAN_BLK)
#define TPB1 128   // pass1: triplets per block

// Scratch (device globals — zero at module load; g_cnt/g_cursor are
// re-zeroed by k_edge at the end of every run => zero on entry always).
__device__ float4   g_rnorm4[MAX_E];
__device__ unsigned g_cnt[MAX_E];
__device__ unsigned g_off[MAX_E];    // block-local exclusive prefix (scan1)
__device__ unsigned g_cursor[MAX_E];
__device__ unsigned g_bsum[MAX_SCAN_BLOCKS];  // exclusive block offsets (scan2)
__device__ float    g_cex[MAX_T];    // exp(logit), CSR(dst)-ordered
__device__ int      g_csrc[MAX_T];   // src ids, CSR(dst)-ordered
__device__ int      g_cdst[MAX_T];   // dst ids, CSR(dst)-ordered

// ---------------------------------------------------------------------------
// prep+count fused: unit bond dirs for i<E; degree histogram for i<T
// ---------------------------------------------------------------------------
__global__ void k_prep_count(const float* __restrict__ r,
                             const int* __restrict__ tdst, int E, int T) {
    int i = blockIdx.x * blockDim.x + threadIdx.x;
    if (i < E) {
        float x = r[3 * i + 0], y = r[3 * i + 1], z = r[3 * i + 2];
        float inv = rsqrtf(x * x + y * y + z * z);
        g_rnorm4[i] = make_float4(x * inv, y * inv, z * inv, 0.0f);
    }
    if (i < T) atomicAdd(&g_cnt[tdst[i]], 1u);
}

// -------- 2-kernel scan; final block-offset add folded into consumers -------
__global__ void k_scan1(int E) {
    __shared__ unsigned sh[SCAN_BLK];
    int i = blockIdx.x * SCAN_BLK + threadIdx.x;
    unsigned v = (i < E) ? g_cnt[i] : 0u;
    sh[threadIdx.x] = v;
    __syncthreads();
    unsigned incl = v;
    for (int ofs = 1; ofs < SCAN_BLK; ofs <<= 1) {
        unsigned add = (threadIdx.x >= ofs) ? sh[threadIdx.x - ofs] : 0u;
        __syncthreads();
        incl += add;
        sh[threadIdx.x] = incl;
        __syncthreads();
    }
    if (i < E) g_off[i] = incl - v;          // block-local exclusive
    if (threadIdx.x == SCAN_BLK - 1) g_bsum[blockIdx.x] = incl;
}

__global__ void k_scan2(int nb) {
    __shared__ unsigned sh[SCAN_BLK];
    unsigned v = (threadIdx.x < nb) ? g_bsum[threadIdx.x] : 0u;
    sh[threadIdx.x] = v;
    __syncthreads();
    unsigned incl = v;
    for (int ofs = 1; ofs < SCAN_BLK; ofs <<= 1) {
        unsigned add = (threadIdx.x >= ofs) ? sh[threadIdx.x - ofs] : 0u;
        __syncthreads();
        incl += add;
        sh[threadIdx.x] = incl;
        __syncthreads();
    }
    if (threadIdx.x < nb) g_bsum[threadIdx.x] = incl - v;   // exclusive blocks
}

__device__ __forceinline__ unsigned edge_base(int e) {
    return g_off[e] + g_bsum[e >> 9];        // SCAN_BLK == 512
}

// ---------------------------------------------------------------------------
// perm: scatter triplets into CSR(dst) order
// ---------------------------------------------------------------------------
__global__ void k_perm(const int* __restrict__ tsrc, const int* __restrict__ tdst, int T) {
    int t = blockIdx.x * blockDim.x + threadIdx.x;
    if (t >= T) return;
    int d = tdst[t];
    unsigned pos = edge_base(d) + atomicAdd(&g_cursor[d], 1u);
    g_csrc[pos] = tsrc[t];
    g_cdst[pos] = d;
}

// ---------------------------------------------------------------------------
// pass1 (R5-verbatim): exp(logit) in CSR order.
//  - xij[src] staged to smem (coalesced, odd stride 65)
//  - xij[dst] direct: CSR adjacency -> few distinct rows/warp, L1-hits
//  - Chebyshev 3-term recurrence (1 FMA/channel)
//  - stores exp(a): softmax needs no max subtraction (|a| << 88;
//    alpha = e^a / sum e^a identically — validated R4-R15)
// ---------------------------------------------------------------------------
__global__ void __launch_bounds__(TPB1)
k_pass1(const float* __restrict__ xij, const float* __restrict__ attn, int T) {
    __shared__ float sx[TPB1 * 65];
    __shared__ float sat[CCH];
    int tid = threadIdx.x;
    int base = blockIdx.x * TPB1;
    if (tid < CCH) sat[tid] = attn[tid];

    int lane = tid & 31, w = tid >> 5;
    for (int j = w; j < TPB1; j += TPB1 / 32) {
        int t = base + j;
        if (t < T) {
            int s = g_csrc[t];
            float2 v = __ldg((const float2*)(xij + (size_t)s * CCH) + lane);
            sx[j * 65 + 2 * lane]     = v.x;
            sx[j * 65 + 2 * lane + 1] = v.y;
        }
    }
    __syncthreads();

    int t = base + tid;
    if (t >= T) return;
    int s = g_csrc[t], d = g_cdst[t];

    float4 rs = __ldg(&g_rnorm4[s]);
    float4 rd = __ldg(&g_rnorm4[d]);
    float cth = rs.x * rd.x + rs.y * rd.y + rs.z * rd.z;
    cth = fminf(fmaxf(cth, -1.0f + 1e-6f), 1.0f - 1e-6f);
    float c2 = 2.0f * cth;
    float zp = cth, zc = 1.0f;   // T_{-1}, T_0

    const float4* xd = (const float4*)(xij + (size_t)d * CCH);
    const float* row = &sx[tid * 65];
    float a = 0.0f;

#pragma unroll
    for (int k = 0; k < CCH / 4; k++) {
        float4 D = __ldg(xd + k);
        float dv[4] = {D.x, D.y, D.z, D.w};
#pragma unroll
        for (int j = 0; j < 4; j++) {
            int c = 4 * k + j;
            float v = zc + row[c] + dv[j];
            float e = __fdividef(v, 1.0f + __expf(-v));   // silu
            a = fmaf(e, sat[c], a);
            float zn = fmaf(c2, zc, -zp);                 // Chebyshev step
            zp = zc; zc = zn;
        }
    }
    g_cex[t] = __expf(a);   // coalesced
}

// ---------------------------------------------------------------------------
// edge (R5-verbatim except base computation): warp-per-edge aggregate.
// ft = (sum ex*x[src]) / sum ex. Lane owns channels {2*lane, 2*lane+1}.
// Resets g_cnt / g_cursor for the next run (self-restoring global state).
// ---------------------------------------------------------------------------
__global__ void __launch_bounds__(256)
k_edge(const float* __restrict__ xij, float* __restrict__ ft, int E) {
    int warp = (blockIdx.x * blockDim.x + threadIdx.x) >> 5;
    int lane = threadIdx.x & 31;
    if (warp >= E) return;

    int base = (int)edge_base(warp);
    int deg  = (int)g_cnt[warp];

    float ax = 0.0f, ay = 0.0f, den = 0.0f;

    int i = 0;
    for (; i + 4 <= deg; i += 4) {
        float e0 = g_cex[base + i + 0], e1 = g_cex[base + i + 1];
        float e2 = g_cex[base + i + 2], e3 = g_cex[base + i + 3];
        int s0 = g_csrc[base + i + 0], s1 = g_csrc[base + i + 1];
        int s2 = g_csrc[base + i + 2], s3 = g_csrc[base + i + 3];
        float2 v0 = __ldg((const float2*)(xij + (size_t)s0 * CCH) + lane);
        float2 v1 = __ldg((const float2*)(xij + (size_t)s1 * CCH) + lane);
        float2 v2 = __ldg((const float2*)(xij + (size_t)s2 * CCH) + lane);
        float2 v3 = __ldg((const float2*)(xij + (size_t)s3 * CCH) + lane);
        den += (e0 + e1) + (e2 + e3);
        ax = fmaf(e0, v0.x, ax); ay = fmaf(e0, v0.y, ay);
        ax = fmaf(e1, v1.x, ax); ay = fmaf(e1, v1.y, ay);
        ax = fmaf(e2, v2.x, ax); ay = fmaf(e2, v2.y, ay);
        ax = fmaf(e3, v3.x, ax); ay = fmaf(e3, v3.y, ay);
    }
    for (; i < deg; i++) {
        float e0 = g_cex[base + i];
        int s0 = g_csrc[base + i];
        float2 v0 = __ldg((const float2*)(xij + (size_t)s0 * CCH) + lane);
        den += e0;
        ax = fmaf(e0, v0.x, ax); ay = fmaf(e0, v0.y, ay);
    }

    float inv = (deg > 0) ? __fdividef(1.0f, den) : 0.0f;
    float2 out = make_float2(ax * inv, ay * inv);
    *((float2*)(ft + (size_t)warp * CCH) + lane) = out;

    if (lane == 0) {                // restore invariant for next run
        g_cnt[warp] = 0u;
        g_cursor[warp] = 0u;
    }
}

// ---------------------------------------------------------------------------
extern "C" void kernel_launch(void* const* d_in, const int* in_sizes, int n_in,
                              void* d_out, int out_size) {
    const float* xij  = (const float*)d_in[0];
    const float* r    = (const float*)d_in[1];
    const float* attn = (const float*)d_in[2];
    const int*   tsrc = (const int*)d_in[3];
    const int*   tdst = (const int*)d_in[4];
    float* ft = (float*)d_out;

    int E = in_sizes[1] / 3;
    int T = in_sizes[3];
    int nsb = (E + SCAN_BLK - 1) / SCAN_BLK;
    int nmx = (T > E) ? T : E;

    k_prep_count<<<(nmx + 255) / 256, 256>>>(r, tdst, E, T);
    k_scan1<<<nsb, SCAN_BLK>>>(E);
    k_scan2<<<1,   SCAN_BLK>>>(nsb);
    k_perm <<<(T + 255) / 256, 256>>>(tsrc, tdst, T);
    k_pass1<<<(T + TPB1 - 1) / TPB1, TPB1>>>(xij, attn, T);
    k_edge <<<(E * 32 + 255) / 256, 256>>>(xij, ft, E);
}